// round 3
// baseline (speedup 1.0000x reference)
#include <cuda_runtime.h>
#include <math.h>

#define T_TOK 4096
#define NH 1024          // hidden
#define NI 512           // intermediate
#define NE 16            // real experts
#define NSLOT 32         // real + zero slots
#define TOPK 4
#define MAXP 4096        // max pairs per expert (<= T)

// ---- static device scratch (no runtime allocation allowed) ----
__device__ int   g_cnt[NE];                       // pairs per expert
__device__ int   g_tok[NE * MAXP];                // token index per pair slot
__device__ float g_wt [NE * MAXP];                // routing weight per pair slot
__device__ int   g_tk_n[T_TOK];                   // real experts chosen per token
__device__ int   g_tk_pair[T_TOK * TOPK];         // pair indices per token (topk order)
__device__ float g_act [(size_t)NE * MAXP * NI];  // SwiGLU activations   (128 MB)
__device__ float g_pout[(size_t)NE * MAXP * NH];  // per-pair down output (256 MB)

// ---------------------------------------------------------------------------
__global__ void reset_kernel() {
    int i = threadIdx.x;
    if (i < NE) g_cnt[i] = 0;
}

// ---------------------------------------------------------------------------
// Router: one block (256 threads) per token.
// logits[32] = x . W_r^T ; softmax ; top-4 on (score+bias) ; weights from raw
// scores. Real experts appended to per-expert lists; zero experts accumulate
// zero_w. Also initializes out = zero_w * x.
__global__ void router_kernel(const float* __restrict__ x,
                              const float* __restrict__ rw,
                              const float* __restrict__ bias,
                              float* __restrict__ out) {
    int t = blockIdx.x;
    __shared__ float sc[NSLOT];
    __shared__ float s_zero;
    int tid  = threadIdx.x;           // 256
    int slot = tid >> 3;              // 32 slots, 8 threads each
    int sub  = tid & 7;
    const float* xr = x  + (size_t)t * NH;
    const float* wr = rw + (size_t)slot * NH;

    float acc = 0.f;
    for (int h = sub * 4; h < NH; h += 32) {
        float4 xv = *reinterpret_cast<const float4*>(xr + h);
        float4 wv = *reinterpret_cast<const float4*>(wr + h);
        acc += xv.x * wv.x + xv.y * wv.y + xv.z * wv.z + xv.w * wv.w;
    }
    acc += __shfl_down_sync(0xffffffffu, acc, 4, 8);
    acc += __shfl_down_sync(0xffffffffu, acc, 2, 8);
    acc += __shfl_down_sync(0xffffffffu, acc, 1, 8);
    if (sub == 0) sc[slot] = acc;
    __syncthreads();

    if (tid == 0) {
        // softmax (fp32, matches reference)
        float mx = -1e30f;
        for (int i = 0; i < NSLOT; i++) mx = fmaxf(mx, sc[i]);
        float e[NSLOT], sum = 0.f;
        for (int i = 0; i < NSLOT; i++) { e[i] = expf(sc[i] - mx); sum += e[i]; }
        float inv = 1.f / sum;
        float sb[NSLOT];
        for (int i = 0; i < NSLOT; i++) {
            sc[i] = e[i] * inv;            // raw score (weight source)
            sb[i] = sc[i] + bias[i];       // selection score
        }
        float zero_w = 0.f;
        int tkn = 0;
        for (int kk = 0; kk < TOPK; kk++) {
            int bi = 0; float bv = -1e30f;
            for (int i = 0; i < NSLOT; i++)
                if (sb[i] > bv) { bv = sb[i]; bi = i; }
            sb[bi] = -1e30f;
            float w = sc[bi];
            if (bi < NE) {
                int s2 = atomicAdd(&g_cnt[bi], 1);
                g_tok[bi * MAXP + s2] = t;
                g_wt [bi * MAXP + s2] = w;
                g_tk_pair[t * TOPK + tkn] = bi * MAXP + s2;
                tkn++;
            } else {
                zero_w += w;
            }
        }
        g_tk_n[t] = tkn;
        s_zero = zero_w;
    }
    __syncthreads();

    float zw = s_zero;
    for (int h = tid; h < NH; h += 256)
        out[(size_t)t * NH + h] = zw * xr[h];
}

// ---------------------------------------------------------------------------
// GEMM1: act[pair, i] = silu(x . w_gate) * (x . w_up)   (per expert group)
// Tiled 64x64, KT=16, 256 threads, 4x4 per thread, two B matrices fused.
#define TM 64
#define TN 64
#define KT 16

__global__ void gemm1_kernel(const float* __restrict__ x,
                             const float* __restrict__ wg,
                             const float* __restrict__ wu) {
    int e    = blockIdx.z;
    int cnt  = g_cnt[e];
    int row0 = blockIdx.y * TM;
    if (row0 >= cnt) return;
    int col0 = blockIdx.x * TN;

    __shared__ float As[KT][TM + 4];
    __shared__ float Bg[KT][TN];
    __shared__ float Bu[KT][TN];

    int tid = threadIdx.x;            // 256
    int am  = tid >> 2;               // 0..63 (row within tile)
    int ak  = (tid & 3) * 4;          // 0,4,8,12
    int bk  = tid >> 4;               // 0..15
    int bn  = (tid & 15) * 4;         // 0..60
    int tx  = tid & 15, ty = tid >> 4;

    int arow  = row0 + am;
    int tokIdx = (arow < cnt) ? g_tok[e * MAXP + arow] : -1;
    const float* wgB = wg + (size_t)e * NH * NI;
    const float* wuB = wu + (size_t)e * NH * NI;

    float accg[4][4] = {}, accu[4][4] = {};

    for (int k0 = 0; k0 < NH; k0 += KT) {
        float4 av = make_float4(0.f, 0.f, 0.f, 0.f);
        if (tokIdx >= 0)
            av = *reinterpret_cast<const float4*>(x + (size_t)tokIdx * NH + k0 + ak);
        As[ak + 0][am] = av.x; As[ak + 1][am] = av.y;
        As[ak + 2][am] = av.z; As[ak + 3][am] = av.w;

        *reinterpret_cast<float4*>(&Bg[bk][bn]) =
            *reinterpret_cast<const float4*>(wgB + (size_t)(k0 + bk) * NI + col0 + bn);
        *reinterpret_cast<float4*>(&Bu[bk][bn]) =
            *reinterpret_cast<const float4*>(wuB + (size_t)(k0 + bk) * NI + col0 + bn);
        __syncthreads();

#pragma unroll
        for (int k = 0; k < KT; k++) {
            float a[4];
#pragma unroll
            for (int i = 0; i < 4; i++) a[i] = As[k][ty * 4 + i];
            float4 bg4 = *reinterpret_cast<const float4*>(&Bg[k][tx * 4]);
            float4 bu4 = *reinterpret_cast<const float4*>(&Bu[k][tx * 4]);
            float bgv[4] = {bg4.x, bg4.y, bg4.z, bg4.w};
            float buv[4] = {bu4.x, bu4.y, bu4.z, bu4.w};
#pragma unroll
            for (int i = 0; i < 4; i++)
#pragma unroll
                for (int j = 0; j < 4; j++) {
                    accg[i][j] += a[i] * bgv[j];
                    accu[i][j] += a[i] * buv[j];
                }
        }
        __syncthreads();
    }

    size_t base = (size_t)e * MAXP;
#pragma unroll
    for (int i = 0; i < 4; i++) {
        int r = row0 + ty * 4 + i;
        if (r < cnt) {
#pragma unroll
            for (int j = 0; j < 4; j++) {
                float g = accg[i][j], u = accu[i][j];
                float s = g / (1.f + expf(-g));
                g_act[(base + r) * NI + col0 + tx * 4 + j] = s * u;
            }
        }
    }
}

// ---------------------------------------------------------------------------
// GEMM2: pout[pair, h] = wt[pair] * (act[pair,:] . w_down[e][:,h])
__global__ void gemm2_kernel(const float* __restrict__ wd) {
    int e    = blockIdx.z;
    int cnt  = g_cnt[e];
    int row0 = blockIdx.y * TM;
    if (row0 >= cnt) return;
    int col0 = blockIdx.x * TN;

    __shared__ float As[KT][TM + 4];
    __shared__ float Bs[KT][TN];

    int tid = threadIdx.x;
    int am  = tid >> 2;
    int ak  = (tid & 3) * 4;
    int bk  = tid >> 4;
    int bn  = (tid & 15) * 4;
    int tx  = tid & 15, ty = tid >> 4;

    int arow = row0 + am;
    bool avalid = (arow < cnt);
    size_t base = (size_t)e * MAXP;
    const float* wdB = wd + (size_t)e * NI * NH;

    float acc[4][4] = {};

    for (int k0 = 0; k0 < NI; k0 += KT) {
        float4 av = make_float4(0.f, 0.f, 0.f, 0.f);
        if (avalid)
            av = *reinterpret_cast<const float4*>(&g_act[(base + arow) * NI + k0 + ak]);
        As[ak + 0][am] = av.x; As[ak + 1][am] = av.y;
        As[ak + 2][am] = av.z; As[ak + 3][am] = av.w;

        *reinterpret_cast<float4*>(&Bs[bk][bn]) =
            *reinterpret_cast<const float4*>(wdB + (size_t)(k0 + bk) * NH + col0 + bn);
        __syncthreads();

#pragma unroll
        for (int k = 0; k < KT; k++) {
            float a[4];
#pragma unroll
            for (int i = 0; i < 4; i++) a[i] = As[k][ty * 4 + i];
            float4 b4 = *reinterpret_cast<const float4*>(&Bs[k][tx * 4]);
            float bv[4] = {b4.x, b4.y, b4.z, b4.w};
#pragma unroll
            for (int i = 0; i < 4; i++)
#pragma unroll
                for (int j = 0; j < 4; j++)
                    acc[i][j] += a[i] * bv[j];
        }
        __syncthreads();
    }

#pragma unroll
    for (int i = 0; i < 4; i++) {
        int r = row0 + ty * 4 + i;
        if (r < cnt) {
            float w = g_wt[e * MAXP + r];
#pragma unroll
            for (int j = 0; j < 4; j++)
                g_pout[(base + r) * NH + col0 + tx * 4 + j] = acc[i][j] * w;
        }
    }
}

// ---------------------------------------------------------------------------
// Combine: out[t] += sum over this token's pairs of pout  (no float atomics,
// summation order fixed by top-k order -> deterministic)
__global__ void combine_kernel(float* __restrict__ out) {
    int t  = blockIdx.x;
    int np = g_tk_n[t];
    int p[TOPK];
    for (int j = 0; j < np; j++) p[j] = g_tk_pair[t * TOPK + j];
    for (int h = threadIdx.x; h < NH; h += 256) {
        float s = 0.f;
        for (int j = 0; j < np; j++)
            s += g_pout[(size_t)p[j] * NH + h];
        out[(size_t)t * NH + h] += s;
    }
}

// ---------------------------------------------------------------------------
extern "C" void kernel_launch(void* const* d_in, const int* in_sizes, int n_in,
                              void* d_out, int out_size) {
    (void)in_sizes; (void)n_in; (void)out_size;
    const float* x    = (const float*)d_in[0];
    const float* rw   = (const float*)d_in[1];
    const float* bias = (const float*)d_in[2];
    const float* wg   = (const float*)d_in[3];
    const float* wu   = (const float*)d_in[4];
    const float* wd   = (const float*)d_in[5];
    float* out = (float*)d_out;

    reset_kernel<<<1, 32>>>();
    router_kernel<<<T_TOK, 256>>>(x, rw, bias, out);

    dim3 g1(NI / TN, T_TOK / TM, NE);
    gemm1_kernel<<<g1, 256>>>(x, wg, wu);

    dim3 g2(NH / TN, T_TOK / TM, NE);
    gemm2_kernel<<<g2, 256>>>(wd);

    combine_kernel<<<T_TOK, 256>>>(out);
}

// round 4
// speedup vs baseline: 1.9147x; 1.9147x over previous
#include <cuda_runtime.h>
#include <math.h>

#define T_TOK 4096
#define NH 1024          // hidden
#define NI 512           // intermediate
#define NE 16            // real experts
#define NSLOT 32         // real + zero slots
#define TOPK 4
#define MAXP 4096        // max pairs per expert (<= T)

// GEMM tiling
#define BM 128
#define BN 64
#define BK 16

// ---- static device scratch (no runtime allocation allowed) ----
__device__ int   g_cnt[NE];                       // pairs per expert
__device__ int   g_tok[NE * MAXP];                // token index per pair slot
__device__ float g_wt [NE * MAXP];                // routing weight per pair slot
__device__ int   g_tk_n[T_TOK];                   // real experts chosen per token
__device__ int   g_tk_pair[T_TOK * TOPK];         // pair indices per token (topk order)
__device__ float g_act [(size_t)NE * MAXP * NI];  // SwiGLU activations
__device__ float g_pout[(size_t)NE * MAXP * NH];  // per-pair down output

// ---------------------------------------------------------------------------
__device__ __forceinline__ unsigned f2tf(float f) {
    unsigned r;
    asm("cvt.rna.tf32.f32 %0, %1;" : "=r"(r) : "f"(f));
    return r;
}

__device__ __forceinline__ void mma_tf32(float* d, const uint4& a, const uint2& b) {
    asm volatile(
        "mma.sync.aligned.m16n8k8.row.col.f32.tf32.tf32.f32 "
        "{%0,%1,%2,%3}, {%4,%5,%6,%7}, {%8,%9}, {%0,%1,%2,%3};"
        : "+f"(d[0]), "+f"(d[1]), "+f"(d[2]), "+f"(d[3])
        : "r"(a.x), "r"(a.y), "r"(a.z), "r"(a.w), "r"(b.x), "r"(b.y));
}

// ---------------------------------------------------------------------------
__global__ void reset_kernel() {
    int i = threadIdx.x;
    if (i < NE) g_cnt[i] = 0;
}

// ---------------------------------------------------------------------------
// Router: one block (256 threads) per token.
__global__ void router_kernel(const float* __restrict__ x,
                              const float* __restrict__ rw,
                              const float* __restrict__ bias,
                              float* __restrict__ out) {
    int t = blockIdx.x;
    __shared__ float sc[NSLOT];
    __shared__ float s_zero;
    int tid  = threadIdx.x;           // 256
    int slot = tid >> 3;              // 32 slots, 8 threads each
    int sub  = tid & 7;
    const float* xr = x  + (size_t)t * NH;
    const float* wr = rw + (size_t)slot * NH;

    float acc = 0.f;
    for (int h = sub * 4; h < NH; h += 32) {
        float4 xv = *reinterpret_cast<const float4*>(xr + h);
        float4 wv = *reinterpret_cast<const float4*>(wr + h);
        acc += xv.x * wv.x + xv.y * wv.y + xv.z * wv.z + xv.w * wv.w;
    }
    acc += __shfl_down_sync(0xffffffffu, acc, 4, 8);
    acc += __shfl_down_sync(0xffffffffu, acc, 2, 8);
    acc += __shfl_down_sync(0xffffffffu, acc, 1, 8);
    if (sub == 0) sc[slot] = acc;
    __syncthreads();

    if (tid == 0) {
        float mx = -1e30f;
        for (int i = 0; i < NSLOT; i++) mx = fmaxf(mx, sc[i]);
        float e[NSLOT], sum = 0.f;
        for (int i = 0; i < NSLOT; i++) { e[i] = expf(sc[i] - mx); sum += e[i]; }
        float inv = 1.f / sum;
        float sb[NSLOT];
        for (int i = 0; i < NSLOT; i++) {
            sc[i] = e[i] * inv;            // raw score (weight source)
            sb[i] = sc[i] + bias[i];       // selection score
        }
        float zero_w = 0.f;
        int tkn = 0;
        for (int kk = 0; kk < TOPK; kk++) {
            int bi = 0; float bv = -1e30f;
            for (int i = 0; i < NSLOT; i++)
                if (sb[i] > bv) { bv = sb[i]; bi = i; }
            sb[bi] = -1e30f;
            float w = sc[bi];
            if (bi < NE) {
                int s2 = atomicAdd(&g_cnt[bi], 1);
                g_tok[bi * MAXP + s2] = t;
                g_wt [bi * MAXP + s2] = w;
                g_tk_pair[t * TOPK + tkn] = bi * MAXP + s2;
                tkn++;
            } else {
                zero_w += w;
            }
        }
        g_tk_n[t] = tkn;
        s_zero = zero_w;
    }
    __syncthreads();

    float zw = s_zero;
    for (int h = tid; h < NH; h += 256)
        out[(size_t)t * NH + h] = zw * xr[h];
}

// ---------------------------------------------------------------------------
// GEMM1 (tensor core tf32): act = silu(X.Wg) * (X.Wu) per expert group.
// Block 128x64, BK=16, 8 warps (4 M x 2 N), warp tile 32x32.
// Fragment-permuted smem: A fragments read with LDS.128, B with LDS.64.
__global__ __launch_bounds__(256, 2) void gemm1_tc(const float* __restrict__ x,
                                                   const float* __restrict__ wg,
                                                   const float* __restrict__ wu) {
    int e    = blockIdx.z;
    int cnt  = g_cnt[e];
    int row0 = blockIdx.y * BM;
    if (row0 >= cnt) return;
    int col0 = blockIdx.x * BN;

    // [k8][tile][lane][reg]
    __shared__ unsigned sA [2 * 8 * 32 * 4];   // 8KB
    __shared__ unsigned sBg[2 * 8 * 32 * 2];   // 4KB
    __shared__ unsigned sBu[2 * 8 * 32 * 2];   // 4KB

    int tid  = threadIdx.x;
    int lane = tid & 31;
    int wid  = tid >> 5;
    int wm   = wid >> 1;      // 0..3
    int wn   = wid & 1;       // 0..1

    // --- A loader precompute: 2 float4 per thread ---
    int tok[2], ar[2], ac[2];
#pragma unroll
    for (int it = 0; it < 2; it++) {
        int f = tid + 256 * it;
        int r = f >> 2;
        ar[it] = r;
        ac[it] = (f & 3) * 4;
        int rr = row0 + r;
        tok[it] = (rr < cnt) ? g_tok[e * MAXP + rr] : -1;
    }
    // --- B loader precompute: 1 float4 per thread per matrix ---
    int bkr = tid >> 4;             // 0..15 (k row within tile)
    int bc  = (tid & 15) * 4;       // 0..60 (col)
    const float* wgB = wg + (size_t)e * NH * NI + (size_t)bkr * NI + col0 + bc;
    const float* wuB = wu + (size_t)e * NH * NI + (size_t)bkr * NI + col0 + bc;
    int bk8  = bkr >> 3;
    int bkk  = bkr & 7;
    int breg = bkk >> 2;
    int bt   = bkk & 3;
    int bnt  = bc >> 3;
    unsigned bbase = (((unsigned)bk8 * 8 + bnt) * 32 + (bc & 7) * 4 + bt) * 2 + breg;

    float dg[2][4][4] = {};
    float du[2][4][4] = {};

    for (int k0 = 0; k0 < NH; k0 += BK) {
        // stage A
#pragma unroll
        for (int it = 0; it < 2; it++) {
            float4 v = make_float4(0.f, 0.f, 0.f, 0.f);
            if (tok[it] >= 0)
                v = *reinterpret_cast<const float4*>(x + (size_t)tok[it] * NH + k0 + ac[it]);
            int r = ar[it], c = ac[it];
            int k8   = c >> 3;
            int reg  = ((r >> 3) & 1) + 2 * ((c >> 2) & 1);
            unsigned base = (((unsigned)k8 * 8 + (r >> 4)) * 32 + (r & 7) * 4) * 4 + reg;
            sA[base + 0]  = f2tf(v.x);
            sA[base + 4]  = f2tf(v.y);
            sA[base + 8]  = f2tf(v.z);
            sA[base + 12] = f2tf(v.w);
        }
        // stage B (gate & up)
        {
            float4 vg = *reinterpret_cast<const float4*>(wgB + (size_t)k0 * NI);
            float4 vu = *reinterpret_cast<const float4*>(wuB + (size_t)k0 * NI);
            sBg[bbase + 0]  = f2tf(vg.x);
            sBg[bbase + 8]  = f2tf(vg.y);
            sBg[bbase + 16] = f2tf(vg.z);
            sBg[bbase + 24] = f2tf(vg.w);
            sBu[bbase + 0]  = f2tf(vu.x);
            sBu[bbase + 8]  = f2tf(vu.y);
            sBu[bbase + 16] = f2tf(vu.z);
            sBu[bbase + 24] = f2tf(vu.w);
        }
        __syncthreads();

#pragma unroll
        for (int k8 = 0; k8 < 2; k8++) {
            uint4 a[2];
#pragma unroll
            for (int m = 0; m < 2; m++)
                a[m] = *reinterpret_cast<uint4*>(&sA[(((unsigned)k8 * 8 + (wm * 2 + m)) * 32 + lane) * 4]);
            uint2 bg[4], bu[4];
#pragma unroll
            for (int n = 0; n < 4; n++) {
                bg[n] = *reinterpret_cast<uint2*>(&sBg[(((unsigned)k8 * 8 + (wn * 4 + n)) * 32 + lane) * 2]);
                bu[n] = *reinterpret_cast<uint2*>(&sBu[(((unsigned)k8 * 8 + (wn * 4 + n)) * 32 + lane) * 2]);
            }
#pragma unroll
            for (int m = 0; m < 2; m++)
#pragma unroll
                for (int n = 0; n < 4; n++) {
                    mma_tf32(dg[m][n], a[m], bg[n]);
                    mma_tf32(du[m][n], a[m], bu[n]);
                }
        }
        __syncthreads();
    }

    // epilogue: silu(g)*u, write to g_act
    size_t base = (size_t)e * MAXP;
    int cg = lane >> 2, ct = lane & 3;
#pragma unroll
    for (int m = 0; m < 2; m++) {
        int rb = row0 + wm * 32 + m * 16 + cg;
#pragma unroll
        for (int n = 0; n < 4; n++) {
            int cb = col0 + wn * 32 + n * 8 + 2 * ct;
            if (rb < cnt) {
                float gv0 = dg[m][n][0], gv1 = dg[m][n][1];
                float s0 = gv0 / (1.f + expf(-gv0));
                float s1 = gv1 / (1.f + expf(-gv1));
                float2 o = make_float2(s0 * du[m][n][0], s1 * du[m][n][1]);
                *reinterpret_cast<float2*>(&g_act[(base + rb) * NI + cb]) = o;
            }
            if (rb + 8 < cnt) {
                float gv2 = dg[m][n][2], gv3 = dg[m][n][3];
                float s2 = gv2 / (1.f + expf(-gv2));
                float s3 = gv3 / (1.f + expf(-gv3));
                float2 o = make_float2(s2 * du[m][n][2], s3 * du[m][n][3]);
                *reinterpret_cast<float2*>(&g_act[(base + rb + 8) * NI + cb]) = o;
            }
        }
    }
}

// ---------------------------------------------------------------------------
// GEMM2 (tensor core tf32): pout = wt * (act . w_down)
__global__ __launch_bounds__(256, 2) void gemm2_tc(const float* __restrict__ wd) {
    int e    = blockIdx.z;
    int cnt  = g_cnt[e];
    int row0 = blockIdx.y * BM;
    if (row0 >= cnt) return;
    int col0 = blockIdx.x * BN;

    __shared__ unsigned sA[2 * 8 * 32 * 4];   // 8KB
    __shared__ unsigned sB[2 * 8 * 32 * 2];   // 4KB

    int tid  = threadIdx.x;
    int lane = tid & 31;
    int wid  = tid >> 5;
    int wm   = wid >> 1;
    int wn   = wid & 1;

    size_t pbase = (size_t)e * MAXP;

    int ar[2], ac[2];
    bool aval[2];
#pragma unroll
    for (int it = 0; it < 2; it++) {
        int f = tid + 256 * it;
        int r = f >> 2;
        ar[it] = r;
        ac[it] = (f & 3) * 4;
        aval[it] = (row0 + r) < cnt;
    }
    int bkr = tid >> 4;
    int bc  = (tid & 15) * 4;
    const float* wdB = wd + (size_t)e * NI * NH + (size_t)bkr * NH + col0 + bc;
    int bk8  = bkr >> 3;
    int bkk  = bkr & 7;
    int breg = bkk >> 2;
    int bt   = bkk & 3;
    int bnt  = bc >> 3;
    unsigned bbase = (((unsigned)bk8 * 8 + bnt) * 32 + (bc & 7) * 4 + bt) * 2 + breg;

    float d[2][4][4] = {};

    for (int k0 = 0; k0 < NI; k0 += BK) {
#pragma unroll
        for (int it = 0; it < 2; it++) {
            float4 v = make_float4(0.f, 0.f, 0.f, 0.f);
            if (aval[it])
                v = *reinterpret_cast<const float4*>(
                        &g_act[(pbase + row0 + ar[it]) * NI + k0 + ac[it]]);
            int r = ar[it], c = ac[it];
            int k8  = c >> 3;
            int reg = ((r >> 3) & 1) + 2 * ((c >> 2) & 1);
            unsigned base = (((unsigned)k8 * 8 + (r >> 4)) * 32 + (r & 7) * 4) * 4 + reg;
            sA[base + 0]  = f2tf(v.x);
            sA[base + 4]  = f2tf(v.y);
            sA[base + 8]  = f2tf(v.z);
            sA[base + 12] = f2tf(v.w);
        }
        {
            float4 vb = *reinterpret_cast<const float4*>(wdB + (size_t)k0 * NH);
            sB[bbase + 0]  = f2tf(vb.x);
            sB[bbase + 8]  = f2tf(vb.y);
            sB[bbase + 16] = f2tf(vb.z);
            sB[bbase + 24] = f2tf(vb.w);
        }
        __syncthreads();

#pragma unroll
        for (int k8 = 0; k8 < 2; k8++) {
            uint4 a[2];
#pragma unroll
            for (int m = 0; m < 2; m++)
                a[m] = *reinterpret_cast<uint4*>(&sA[(((unsigned)k8 * 8 + (wm * 2 + m)) * 32 + lane) * 4]);
            uint2 b[4];
#pragma unroll
            for (int n = 0; n < 4; n++)
                b[n] = *reinterpret_cast<uint2*>(&sB[(((unsigned)k8 * 8 + (wn * 4 + n)) * 32 + lane) * 2]);
#pragma unroll
            for (int m = 0; m < 2; m++)
#pragma unroll
                for (int n = 0; n < 4; n++)
                    mma_tf32(d[m][n], a[m], b[n]);
        }
        __syncthreads();
    }

    int cg = lane >> 2, ct = lane & 3;
#pragma unroll
    for (int m = 0; m < 2; m++) {
        int rb = row0 + wm * 32 + m * 16 + cg;
        float w0 = (rb     < cnt) ? g_wt[e * MAXP + rb]     : 0.f;
        float w1 = (rb + 8 < cnt) ? g_wt[e * MAXP + rb + 8] : 0.f;
#pragma unroll
        for (int n = 0; n < 4; n++) {
            int cb = col0 + wn * 32 + n * 8 + 2 * ct;
            if (rb < cnt) {
                float2 o = make_float2(d[m][n][0] * w0, d[m][n][1] * w0);
                *reinterpret_cast<float2*>(&g_pout[(pbase + rb) * NH + cb]) = o;
            }
            if (rb + 8 < cnt) {
                float2 o = make_float2(d[m][n][2] * w1, d[m][n][3] * w1);
                *reinterpret_cast<float2*>(&g_pout[(pbase + rb + 8) * NH + cb]) = o;
            }
        }
    }
}

// ---------------------------------------------------------------------------
// Combine: out[t] += sum of this token's pair outputs (deterministic order).
__global__ void combine_kernel(float* __restrict__ out) {
    int t  = blockIdx.x;
    int np = g_tk_n[t];
    int p[TOPK];
    for (int j = 0; j < np; j++) p[j] = g_tk_pair[t * TOPK + j];
    for (int h = threadIdx.x; h < NH; h += 256) {
        float s = 0.f;
        for (int j = 0; j < np; j++)
            s += g_pout[(size_t)p[j] * NH + h];
        out[(size_t)t * NH + h] += s;
    }
}

// ---------------------------------------------------------------------------
extern "C" void kernel_launch(void* const* d_in, const int* in_sizes, int n_in,
                              void* d_out, int out_size) {
    (void)in_sizes; (void)n_in; (void)out_size;
    const float* x    = (const float*)d_in[0];
    const float* rw   = (const float*)d_in[1];
    const float* bias = (const float*)d_in[2];
    const float* wg   = (const float*)d_in[3];
    const float* wu   = (const float*)d_in[4];
    const float* wd   = (const float*)d_in[5];
    float* out = (float*)d_out;

    reset_kernel<<<1, 32>>>();
    router_kernel<<<T_TOK, 256>>>(x, rw, bias, out);

    dim3 g1(NI / BN, T_TOK / BM, NE);
    gemm1_tc<<<g1, 256>>>(x, wg, wu);

    dim3 g2(NH / BN, T_TOK / BM, NE);
    gemm2_tc<<<g2, 256>>>(wd);

    combine_kernel<<<T_TOK, 256>>>(out);
}

// round 5
// speedup vs baseline: 2.0785x; 1.0856x over previous
#include <cuda_runtime.h>
#include <math.h>

#define T_TOK 4096
#define NH 1024          // hidden
#define NI 512           // intermediate
#define NE 16            // real experts
#define NSLOT 32         // real + zero slots
#define TOPK 4
#define MAXP 4096        // max pairs per expert (<= T)

// GEMM tiling
#define BM 128
#define BN 64
#define BK 16

// ---- static device scratch (no runtime allocation allowed) ----
__device__ int   g_cnt[NE];                       // pairs per expert
__device__ int   g_tok[NE * MAXP];                // token index per pair slot
__device__ float g_wt [NE * MAXP];                // routing weight per pair slot
__device__ int   g_tk_n[T_TOK];                   // real experts chosen per token
__device__ int   g_tk_pair[T_TOK * TOPK];         // pair indices per token (topk order)
__device__ float g_act [(size_t)NE * MAXP * NI];  // SwiGLU activations
__device__ float g_pout[(size_t)NE * MAXP * NH];  // per-pair down output

// ---------------------------------------------------------------------------
__device__ __forceinline__ unsigned f2tf(float f) {
    unsigned r;
    asm("cvt.rna.tf32.f32 %0, %1;" : "=r"(r) : "f"(f));
    return r;
}

__device__ __forceinline__ void mma_tf32(float* d, const uint4& a, const uint2& b) {
    asm volatile(
        "mma.sync.aligned.m16n8k8.row.col.f32.tf32.tf32.f32 "
        "{%0,%1,%2,%3}, {%4,%5,%6,%7}, {%8,%9}, {%0,%1,%2,%3};"
        : "+f"(d[0]), "+f"(d[1]), "+f"(d[2]), "+f"(d[3])
        : "r"(a.x), "r"(a.y), "r"(a.z), "r"(a.w), "r"(b.x), "r"(b.y));
}

// ---------------------------------------------------------------------------
__global__ void reset_kernel() {
    int i = threadIdx.x;
    if (i < NE) g_cnt[i] = 0;
}

// ---------------------------------------------------------------------------
// Router: one block (256 threads) per token.
__global__ void router_kernel(const float* __restrict__ x,
                              const float* __restrict__ rw,
                              const float* __restrict__ bias,
                              float* __restrict__ out) {
    int t = blockIdx.x;
    __shared__ float sc[NSLOT];
    __shared__ float s_zero;
    int tid  = threadIdx.x;           // 256
    int slot = tid >> 3;              // 32 slots, 8 threads each
    int sub  = tid & 7;
    const float* xr = x  + (size_t)t * NH;
    const float* wr = rw + (size_t)slot * NH;

    float acc = 0.f;
    for (int h = sub * 4; h < NH; h += 32) {
        float4 xv = *reinterpret_cast<const float4*>(xr + h);
        float4 wv = *reinterpret_cast<const float4*>(wr + h);
        acc += xv.x * wv.x + xv.y * wv.y + xv.z * wv.z + xv.w * wv.w;
    }
    acc += __shfl_down_sync(0xffffffffu, acc, 4, 8);
    acc += __shfl_down_sync(0xffffffffu, acc, 2, 8);
    acc += __shfl_down_sync(0xffffffffu, acc, 1, 8);
    if (sub == 0) sc[slot] = acc;
    __syncthreads();

    if (tid == 0) {
        float mx = -1e30f;
        for (int i = 0; i < NSLOT; i++) mx = fmaxf(mx, sc[i]);
        float e[NSLOT], sum = 0.f;
        for (int i = 0; i < NSLOT; i++) { e[i] = expf(sc[i] - mx); sum += e[i]; }
        float inv = 1.f / sum;
        float sb[NSLOT];
        for (int i = 0; i < NSLOT; i++) {
            sc[i] = e[i] * inv;            // raw score (weight source)
            sb[i] = sc[i] + bias[i];       // selection score
        }
        float zero_w = 0.f;
        int tkn = 0;
        for (int kk = 0; kk < TOPK; kk++) {
            int bi = 0; float bv = -1e30f;
            for (int i = 0; i < NSLOT; i++)
                if (sb[i] > bv) { bv = sb[i]; bi = i; }
            sb[bi] = -1e30f;
            float w = sc[bi];
            if (bi < NE) {
                int s2 = atomicAdd(&g_cnt[bi], 1);
                g_tok[bi * MAXP + s2] = t;
                g_wt [bi * MAXP + s2] = w;
                g_tk_pair[t * TOPK + tkn] = bi * MAXP + s2;
                tkn++;
            } else {
                zero_w += w;
            }
        }
        g_tk_n[t] = tkn;
        s_zero = zero_w;
    }
    __syncthreads();

    float zw = s_zero;
    for (int h = tid; h < NH; h += 256)
        out[(size_t)t * NH + h] = zw * xr[h];
}

// ---------------------------------------------------------------------------
// GEMM1 (tf32 TC, double-buffered + register prefetch):
// act = silu(X.Wg) * (X.Wu) per expert group.
// Block 128x64, BK=16, 8 warps (4 M x 2 N), warp tile 32x32.
#define SA_BUF (8 * 32 * 4 * 2)   // per-buffer unsigned count for A  (k8=2)
#define SB_BUF (8 * 32 * 2 * 2)   // per-buffer unsigned count for B  (k8=2)

__global__ __launch_bounds__(256) void gemm1_tc(const float* __restrict__ x,
                                                const float* __restrict__ wg,
                                                const float* __restrict__ wu) {
    int e    = blockIdx.z;
    int cnt  = g_cnt[e];
    int row0 = blockIdx.y * BM;
    if (row0 >= cnt) return;
    int col0 = blockIdx.x * BN;

    __shared__ unsigned sA [2 * SA_BUF];   // 16KB
    __shared__ unsigned sBg[2 * SB_BUF];   // 8KB
    __shared__ unsigned sBu[2 * SB_BUF];   // 8KB

    int tid  = threadIdx.x;
    int lane = tid & 31;
    int wid  = tid >> 5;
    int wm   = wid >> 1;      // 0..3
    int wn   = wid & 1;       // 0..1

    // --- A loader precompute: 2 float4 per thread ---
    int tok[2];
    unsigned abase[2];
    int ac[2];
#pragma unroll
    for (int it = 0; it < 2; it++) {
        int f = tid + 256 * it;
        int r = f >> 2;
        int c = (f & 3) * 4;
        ac[it] = c;
        int rr = row0 + r;
        tok[it] = (rr < cnt) ? g_tok[e * MAXP + rr] : -1;
        int k8  = c >> 3;
        int reg = ((r >> 3) & 1) + 2 * ((c >> 2) & 1);
        abase[it] = (((unsigned)k8 * 8 + (r >> 4)) * 32 + (r & 7) * 4) * 4 + reg;
    }
    // --- B loader precompute ---
    int bkr = tid >> 4;             // 0..15 (k row within tile)
    int bc  = (tid & 15) * 4;       // 0..60 (col)
    const float* wgB = wg + (size_t)e * NH * NI + (size_t)bkr * NI + col0 + bc;
    const float* wuB = wu + (size_t)e * NH * NI + (size_t)bkr * NI + col0 + bc;
    int bk8  = bkr >> 3;
    int bkk  = bkr & 7;
    int breg = bkk >> 2;
    int bt   = bkk & 3;
    int bnt  = bc >> 3;
    unsigned bbase = (((unsigned)bk8 * 8 + bnt) * 32 + (bc & 7) * 4 + bt) * 2 + breg;

    float dg[2][4][4] = {};
    float du[2][4][4] = {};

    float4 pA[2], pG, pU;
    // prologue: prefetch k0=0
#pragma unroll
    for (int it = 0; it < 2; it++) {
        pA[it] = make_float4(0.f, 0.f, 0.f, 0.f);
        if (tok[it] >= 0)
            pA[it] = *reinterpret_cast<const float4*>(x + (size_t)tok[it] * NH + ac[it]);
    }
    pG = *reinterpret_cast<const float4*>(wgB);
    pU = *reinterpret_cast<const float4*>(wuB);
    // stage into buffer 0
#pragma unroll
    for (int it = 0; it < 2; it++) {
        sA[abase[it] + 0]  = f2tf(pA[it].x);
        sA[abase[it] + 4]  = f2tf(pA[it].y);
        sA[abase[it] + 8]  = f2tf(pA[it].z);
        sA[abase[it] + 12] = f2tf(pA[it].w);
    }
    sBg[bbase + 0]  = f2tf(pG.x);  sBg[bbase + 8]  = f2tf(pG.y);
    sBg[bbase + 16] = f2tf(pG.z);  sBg[bbase + 24] = f2tf(pG.w);
    sBu[bbase + 0]  = f2tf(pU.x);  sBu[bbase + 8]  = f2tf(pU.y);
    sBu[bbase + 16] = f2tf(pU.z);  sBu[bbase + 24] = f2tf(pU.w);
    __syncthreads();

    const int NIT = NH / BK;  // 64
    for (int iter = 0; iter < NIT; iter++) {
        int buf = iter & 1;
        // prefetch next tile's gmem data (LDGs fly under the MMAs below)
        if (iter + 1 < NIT) {
            int k0 = (iter + 1) * BK;
#pragma unroll
            for (int it = 0; it < 2; it++) {
                pA[it] = make_float4(0.f, 0.f, 0.f, 0.f);
                if (tok[it] >= 0)
                    pA[it] = *reinterpret_cast<const float4*>(
                                 x + (size_t)tok[it] * NH + k0 + ac[it]);
            }
            pG = *reinterpret_cast<const float4*>(wgB + (size_t)k0 * NI);
            pU = *reinterpret_cast<const float4*>(wuB + (size_t)k0 * NI);
        }

        unsigned aoff = (unsigned)buf * SA_BUF;
        unsigned boff = (unsigned)buf * SB_BUF;
#pragma unroll
        for (int k8 = 0; k8 < 2; k8++) {
            uint4 a[2];
#pragma unroll
            for (int m = 0; m < 2; m++)
                a[m] = *reinterpret_cast<uint4*>(
                    &sA[aoff + (((unsigned)k8 * 8 + (wm * 2 + m)) * 32 + lane) * 4]);
            uint2 bg[4], bu[4];
#pragma unroll
            for (int n = 0; n < 4; n++) {
                bg[n] = *reinterpret_cast<uint2*>(
                    &sBg[boff + (((unsigned)k8 * 8 + (wn * 4 + n)) * 32 + lane) * 2]);
                bu[n] = *reinterpret_cast<uint2*>(
                    &sBu[boff + (((unsigned)k8 * 8 + (wn * 4 + n)) * 32 + lane) * 2]);
            }
#pragma unroll
            for (int m = 0; m < 2; m++)
#pragma unroll
                for (int n = 0; n < 4; n++) {
                    mma_tf32(dg[m][n], a[m], bg[n]);
                    mma_tf32(du[m][n], a[m], bu[n]);
                }
        }

        if (iter + 1 < NIT) {
            __syncthreads();   // everyone finished reading the other buffer
            unsigned na = (unsigned)(buf ^ 1) * SA_BUF;
            unsigned nb = (unsigned)(buf ^ 1) * SB_BUF;
#pragma unroll
            for (int it = 0; it < 2; it++) {
                sA[na + abase[it] + 0]  = f2tf(pA[it].x);
                sA[na + abase[it] + 4]  = f2tf(pA[it].y);
                sA[na + abase[it] + 8]  = f2tf(pA[it].z);
                sA[na + abase[it] + 12] = f2tf(pA[it].w);
            }
            sBg[nb + bbase + 0]  = f2tf(pG.x);  sBg[nb + bbase + 8]  = f2tf(pG.y);
            sBg[nb + bbase + 16] = f2tf(pG.z);  sBg[nb + bbase + 24] = f2tf(pG.w);
            sBu[nb + bbase + 0]  = f2tf(pU.x);  sBu[nb + bbase + 8]  = f2tf(pU.y);
            sBu[nb + bbase + 16] = f2tf(pU.z);  sBu[nb + bbase + 24] = f2tf(pU.w);
            __syncthreads();   // staged data visible
        }
    }

    // epilogue: silu(g)*u, write to g_act
    size_t base = (size_t)e * MAXP;
    int cg = lane >> 2, ct = lane & 3;
#pragma unroll
    for (int m = 0; m < 2; m++) {
        int rb = row0 + wm * 32 + m * 16 + cg;
#pragma unroll
        for (int n = 0; n < 4; n++) {
            int cb = col0 + wn * 32 + n * 8 + 2 * ct;
            if (rb < cnt) {
                float gv0 = dg[m][n][0], gv1 = dg[m][n][1];
                float s0 = gv0 / (1.f + expf(-gv0));
                float s1 = gv1 / (1.f + expf(-gv1));
                float2 o = make_float2(s0 * du[m][n][0], s1 * du[m][n][1]);
                *reinterpret_cast<float2*>(&g_act[(base + rb) * NI + cb]) = o;
            }
            if (rb + 8 < cnt) {
                float gv2 = dg[m][n][2], gv3 = dg[m][n][3];
                float s2 = gv2 / (1.f + expf(-gv2));
                float s3 = gv3 / (1.f + expf(-gv3));
                float2 o = make_float2(s2 * du[m][n][2], s3 * du[m][n][3]);
                *reinterpret_cast<float2*>(&g_act[(base + rb + 8) * NI + cb]) = o;
            }
        }
    }
}

// ---------------------------------------------------------------------------
// GEMM2 (tf32 TC, double-buffered + register prefetch):
// pout = wt * (act . w_down)
__global__ __launch_bounds__(256) void gemm2_tc(const float* __restrict__ wd) {
    int e    = blockIdx.z;
    int cnt  = g_cnt[e];
    int row0 = blockIdx.y * BM;
    if (row0 >= cnt) return;
    int col0 = blockIdx.x * BN;

    __shared__ unsigned sA[2 * SA_BUF];   // 16KB
    __shared__ unsigned sB[2 * SB_BUF];   // 8KB

    int tid  = threadIdx.x;
    int lane = tid & 31;
    int wid  = tid >> 5;
    int wm   = wid >> 1;
    int wn   = wid & 1;

    size_t pbase = (size_t)e * MAXP;

    int ac[2];
    bool aval[2];
    unsigned abase[2];
    const float* aptr[2];
#pragma unroll
    for (int it = 0; it < 2; it++) {
        int f = tid + 256 * it;
        int r = f >> 2;
        int c = (f & 3) * 4;
        ac[it] = c;
        aval[it] = (row0 + r) < cnt;
        aptr[it] = &g_act[(pbase + row0 + r) * NI + c];
        int k8  = c >> 3;
        int reg = ((r >> 3) & 1) + 2 * ((c >> 2) & 1);
        abase[it] = (((unsigned)k8 * 8 + (r >> 4)) * 32 + (r & 7) * 4) * 4 + reg;
    }
    int bkr = tid >> 4;
    int bc  = (tid & 15) * 4;
    const float* wdB = wd + (size_t)e * NI * NH + (size_t)bkr * NH + col0 + bc;
    int bk8  = bkr >> 3;
    int bkk  = bkr & 7;
    int breg = bkk >> 2;
    int bt   = bkk & 3;
    int bnt  = bc >> 3;
    unsigned bbase = (((unsigned)bk8 * 8 + bnt) * 32 + (bc & 7) * 4 + bt) * 2 + breg;

    float d[2][4][4] = {};

    float4 pA[2], pB;
#pragma unroll
    for (int it = 0; it < 2; it++) {
        pA[it] = make_float4(0.f, 0.f, 0.f, 0.f);
        if (aval[it]) pA[it] = *reinterpret_cast<const float4*>(aptr[it]);
    }
    pB = *reinterpret_cast<const float4*>(wdB);
#pragma unroll
    for (int it = 0; it < 2; it++) {
        sA[abase[it] + 0]  = f2tf(pA[it].x);
        sA[abase[it] + 4]  = f2tf(pA[it].y);
        sA[abase[it] + 8]  = f2tf(pA[it].z);
        sA[abase[it] + 12] = f2tf(pA[it].w);
    }
    sB[bbase + 0]  = f2tf(pB.x);  sB[bbase + 8]  = f2tf(pB.y);
    sB[bbase + 16] = f2tf(pB.z);  sB[bbase + 24] = f2tf(pB.w);
    __syncthreads();

    const int NIT = NI / BK;  // 32
    for (int iter = 0; iter < NIT; iter++) {
        int buf = iter & 1;
        if (iter + 1 < NIT) {
            int k0 = (iter + 1) * BK;
#pragma unroll
            for (int it = 0; it < 2; it++) {
                pA[it] = make_float4(0.f, 0.f, 0.f, 0.f);
                if (aval[it])
                    pA[it] = *reinterpret_cast<const float4*>(aptr[it] + k0);
            }
            pB = *reinterpret_cast<const float4*>(wdB + (size_t)k0 * NH);
        }

        unsigned aoff = (unsigned)buf * SA_BUF;
        unsigned boff = (unsigned)buf * SB_BUF;
#pragma unroll
        for (int k8 = 0; k8 < 2; k8++) {
            uint4 a[2];
#pragma unroll
            for (int m = 0; m < 2; m++)
                a[m] = *reinterpret_cast<uint4*>(
                    &sA[aoff + (((unsigned)k8 * 8 + (wm * 2 + m)) * 32 + lane) * 4]);
            uint2 b[4];
#pragma unroll
            for (int n = 0; n < 4; n++)
                b[n] = *reinterpret_cast<uint2*>(
                    &sB[boff + (((unsigned)k8 * 8 + (wn * 4 + n)) * 32 + lane) * 2]);
#pragma unroll
            for (int m = 0; m < 2; m++)
#pragma unroll
                for (int n = 0; n < 4; n++)
                    mma_tf32(d[m][n], a[m], b[n]);
        }

        if (iter + 1 < NIT) {
            __syncthreads();
            unsigned na = (unsigned)(buf ^ 1) * SA_BUF;
            unsigned nb = (unsigned)(buf ^ 1) * SB_BUF;
#pragma unroll
            for (int it = 0; it < 2; it++) {
                sA[na + abase[it] + 0]  = f2tf(pA[it].x);
                sA[na + abase[it] + 4]  = f2tf(pA[it].y);
                sA[na + abase[it] + 8]  = f2tf(pA[it].z);
                sA[na + abase[it] + 12] = f2tf(pA[it].w);
            }
            sB[nb + bbase + 0]  = f2tf(pB.x);  sB[nb + bbase + 8]  = f2tf(pB.y);
            sB[nb + bbase + 16] = f2tf(pB.z);  sB[nb + bbase + 24] = f2tf(pB.w);
            __syncthreads();
        }
    }

    int cg = lane >> 2, ct = lane & 3;
#pragma unroll
    for (int m = 0; m < 2; m++) {
        int rb = row0 + wm * 32 + m * 16 + cg;
        float w0 = (rb     < cnt) ? g_wt[e * MAXP + rb]     : 0.f;
        float w1 = (rb + 8 < cnt) ? g_wt[e * MAXP + rb + 8] : 0.f;
#pragma unroll
        for (int n = 0; n < 4; n++) {
            int cb = col0 + wn * 32 + n * 8 + 2 * ct;
            if (rb < cnt) {
                float2 o = make_float2(d[m][n][0] * w0, d[m][n][1] * w0);
                *reinterpret_cast<float2*>(&g_pout[(pbase + rb) * NH + cb]) = o;
            }
            if (rb + 8 < cnt) {
                float2 o = make_float2(d[m][n][2] * w1, d[m][n][3] * w1);
                *reinterpret_cast<float2*>(&g_pout[(pbase + rb + 8) * NH + cb]) = o;
            }
        }
    }
}

// ---------------------------------------------------------------------------
// Combine: out[t] += sum of this token's pair outputs (deterministic order).
__global__ void combine_kernel(float* __restrict__ out) {
    int t  = blockIdx.x;
    int np = g_tk_n[t];
    int p[TOPK];
    for (int j = 0; j < np; j++) p[j] = g_tk_pair[t * TOPK + j];
    for (int h = threadIdx.x; h < NH; h += 256) {
        float s = 0.f;
        for (int j = 0; j < np; j++)
            s += g_pout[(size_t)p[j] * NH + h];
        out[(size_t)t * NH + h] += s;
    }
}

// ---------------------------------------------------------------------------
extern "C" void kernel_launch(void* const* d_in, const int* in_sizes, int n_in,
                              void* d_out, int out_size) {
    (void)in_sizes; (void)n_in; (void)out_size;
    const float* x    = (const float*)d_in[0];
    const float* rw   = (const float*)d_in[1];
    const float* bias = (const float*)d_in[2];
    const float* wg   = (const float*)d_in[3];
    const float* wu   = (const float*)d_in[4];
    const float* wd   = (const float*)d_in[5];
    float* out = (float*)d_out;

    reset_kernel<<<1, 32>>>();
    router_kernel<<<T_TOK, 256>>>(x, rw, bias, out);

    dim3 g1(NI / BN, T_TOK / BM, NE);
    gemm1_tc<<<g1, 256>>>(x, wg, wu);

    dim3 g2(NH / BN, T_TOK / BM, NE);
    gemm2_tc<<<g2, 256>>>(wd);

    combine_kernel<<<T_TOK, 256>>>(out);
}